// round 12
// baseline (speedup 1.0000x reference)
#include <cuda_runtime.h>
#include <cuda_fp16.h>
#include <cstdint>

#define NN 2048
#define NT 10
#define KK 5
constexpr float LN_EPS = 1e-5f;

// GEMM tiling: CTA 128x128, BK=64, 4 warps (2x2), warp tile 64x64, 3 stages
// 2 CTAs/SM. ALL work (prep + 3 GEMMs + LN) fused into ONE launch with
// per-(phase,t) flag dependencies.
#define BM 128
#define BN 128
#define BK 64
#define KCH (NN / BK)                          // 32
#define STAGE_BYTES (BM * 128 + BK * 256)      // A 16KB + B 16KB = 32KB
#define SMEM_DYN (3 * STAGE_BYTES + 1024)      // 99328
#define TILES_PER_T 256                        // 16x16 GEMM tiles; also 256 row-blocks
#define CTAS_PER_PHASE (NT * TILES_PER_T)      // 2560
// phases: 0=prep, 1=G2, 2=G3, 3=R, 4=LN

// Scratch (__device__ globals; allocation-free rule)
__device__ __half g_Gh [(size_t)NT * NN * NN];  // G_norm
__device__ __half g_G2h[(size_t)NT * NN * NN];  // G^2
__device__ __half g_G3h[(size_t)NT * NN * NN];  // G^3
__device__ __half g_Qh [(size_t)NT * NN * NN];  // Q = a5 G^2 + a4 G + a3 I
__device__ float  g_acc[(size_t)NT * NN * NN];  // pre-LN accumulator (fp32)
__device__ float  g_coef[NT][6];
__device__ int    g_done[4][NT];                // completion counters per phase 0..3

__device__ __forceinline__ float clip01(float v) { return fminf(fmaxf(v, 0.f), 1.f); }

__device__ __forceinline__ void cpasync16(uint32_t s, const void* g) {
    asm volatile("cp.async.cg.shared.global [%0], [%1], 16;\n" :: "r"(s), "l"(g));
}
__device__ __forceinline__ void ldsm4(uint32_t* r, uint32_t addr) {
    asm volatile("ldmatrix.sync.aligned.m8n8.x4.shared.b16 {%0,%1,%2,%3}, [%4];"
                 : "=r"(r[0]), "=r"(r[1]), "=r"(r[2]), "=r"(r[3]) : "r"(addr));
}
__device__ __forceinline__ void ldsm4t(uint32_t* r, uint32_t addr) {
    asm volatile("ldmatrix.sync.aligned.m8n8.x4.trans.shared.b16 {%0,%1,%2,%3}, [%4];"
                 : "=r"(r[0]), "=r"(r[1]), "=r"(r[2]), "=r"(r[3]) : "r"(addr));
}
__device__ __forceinline__ void mma16816(float* c, const uint32_t* a,
                                         uint32_t b0, uint32_t b1) {
    asm volatile("mma.sync.aligned.m16n8k16.row.col.f32.f16.f16.f32 "
                 "{%0,%1,%2,%3}, {%4,%5,%6,%7}, {%8,%9}, {%0,%1,%2,%3};"
                 : "+f"(c[0]), "+f"(c[1]), "+f"(c[2]), "+f"(c[3])
                 : "r"(a[0]), "r"(a[1]), "r"(a[2]), "r"(a[3]), "r"(b0), "r"(b1));
}

// -------------------------------------------------------------------------
// coef: per t, polynomial coefficients; zero dependency counters
// -------------------------------------------------------------------------
__global__ void coef_kernel(const float* __restrict__ w) {
    int t = threadIdx.x;
    if (t < 4 * NT) ((int*)g_done)[t] = 0;
    if (t >= NT) return;
    float c[6] = {1.f, 0.f, 0.f, 0.f, 0.f, 0.f};
    float a[6] = {0.f, 0.f, 0.f, 0.f, 0.f, 0.f};
    for (int k = 0; k < KK; k++) {
        float wk = clip01(w[t * KK + k]);
        float nc[6];
        nc[0] = 1.f - wk;
#pragma unroll
        for (int m = 1; m < 6; m++) nc[m] = wk * c[m - 1];
#pragma unroll
        for (int m = 0; m < 6; m++) { c[m] = nc[m]; a[m] += nc[m]; }
    }
#pragma unroll
    for (int m = 0; m < 6; m++) g_coef[t][m] = a[m];
}

// -------------------------------------------------------------------------
// Mega-fused kernel: phase 0 prep, 1..3 GEMM chain, 4 LayerNorm.
// -------------------------------------------------------------------------
__global__ __launch_bounds__(128, 2) void fused_kernel(
    const float* __restrict__ x,
    const float* __restrict__ gamma,
    const float* __restrict__ beta,
    float* __restrict__ out
) {
    extern __shared__ unsigned char dsm_raw[];
    uint32_t dsm = (uint32_t)__cvta_generic_to_shared(dsm_raw);
    uint32_t smem_base = (dsm + 1023) & ~1023u;
    float* stg = reinterpret_cast<float*>(dsm_raw + (smem_base - dsm));

    __shared__ float red[2][4];

    int tid = threadIdx.x;
    int l = tid & 31, wid = tid >> 5;

    int bid = blockIdx.x;
    int phase = bid / CTAS_PER_PHASE;
    int rem = bid - phase * CTAS_PER_PHASE;
    int t = rem / TILES_PER_T;
    int sub = rem - t * TILES_PER_T;
    size_t baseT = (size_t)t * NN * NN;

    // ===================== phase 0: prep (8 rows per CTA) ================
    if (phase == 0) {
#pragma unroll 1
        for (int rr = 0; rr < 8; rr++) {
            int i = sub * 8 + rr;
            const float4* xr = reinterpret_cast<const float4*>(
                x + ((size_t)i * NT + t) * NN);
            float4 v[4];
            float s = 0.f;
#pragma unroll
            for (int q = 0; q < 4; q++) {
                v[q] = xr[tid + q * 128];
                s += v[q].x + v[q].y + v[q].z + v[q].w;
            }
            for (int o = 16; o; o >>= 1) s += __shfl_down_sync(0xffffffffu, s, o);
            if (l == 0) red[0][wid] = s;
            __syncthreads();
            float inv = 1.f / (red[0][0] + red[0][1] + red[0][2] + red[0][3] + 1e-8f);
            size_t base = (baseT + (size_t)i * NN);
#pragma unroll
            for (int q = 0; q < 4; q++) {
                int j0 = (tid + q * 128) * 4;
                *reinterpret_cast<__half2*>(&g_Gh[base + j0]) =
                    __floats2half2_rn(v[q].x * inv, v[q].y * inv);
                *reinterpret_cast<__half2*>(&g_Gh[base + j0 + 2]) =
                    __floats2half2_rn(v[q].z * inv, v[q].w * inv);
            }
            __syncthreads();
        }
        if (tid == 0) {
            __threadfence();
            atomicAdd(&g_done[0][t], 1);
        }
        return;
    }

    // ===================== phase 4: LayerNorm (8 rows per CTA) ===========
    if (phase == 4) {
        if (tid == 0) {
            volatile int* flag = &g_done[3][t];
            while (atomicAdd((int*)flag, 0) < TILES_PER_T) __nanosleep(128);
            __threadfence();
        }
        __syncthreads();
#pragma unroll 1
        for (int rr = 0; rr < 8; rr++) {
            int i = sub * 8 + rr;
            const float4* a = reinterpret_cast<const float4*>(
                g_acc + baseT + (size_t)i * NN);
            float4 v[4];
            float s = 0.f, ss = 0.f;
#pragma unroll
            for (int q = 0; q < 4; q++) {
                v[q] = a[tid + q * 128];
                s  += v[q].x + v[q].y + v[q].z + v[q].w;
                ss += v[q].x * v[q].x + v[q].y * v[q].y
                    + v[q].z * v[q].z + v[q].w * v[q].w;
            }
            for (int o = 16; o; o >>= 1) {
                s  += __shfl_down_sync(0xffffffffu, s, o);
                ss += __shfl_down_sync(0xffffffffu, ss, o);
            }
            if (l == 0) { red[0][wid] = s; red[1][wid] = ss; }
            __syncthreads();
            float sum  = red[0][0] + red[0][1] + red[0][2] + red[0][3];
            float sumq = red[1][0] + red[1][1] + red[1][2] + red[1][3];
            float mu = sum * (1.f / NN);
            float var = sumq * (1.f / NN) - mu * mu;
            float rstd = rsqrtf(var + LN_EPS);
            float4* o4 = reinterpret_cast<float4*>(out + ((size_t)i * NT + t) * NN);
            const float4* gm = reinterpret_cast<const float4*>(gamma);
            const float4* bt = reinterpret_cast<const float4*>(beta);
#pragma unroll
            for (int q = 0; q < 4; q++) {
                int idx = tid + q * 128;
                float4 g = gm[idx], b = bt[idx];
                float4 r;
                r.x = (v[q].x - mu) * rstd * g.x + b.x;
                r.y = (v[q].y - mu) * rstd * g.y + b.y;
                r.z = (v[q].z - mu) * rstd * g.z + b.z;
                r.w = (v[q].w - mu) * rstd * g.w + b.w;
                o4[idx] = r;
            }
            __syncthreads();
        }
        return;
    }

    // ===================== phases 1..3: GEMM chain =======================
    int gp = phase - 1;                 // 0: G2=G*G, 1: G3=G2*G, 2: R=Q*G3
    int m0 = (sub >> 4) * BM;
    int n0 = (sub & 15) * BN;

    // wait for producer phase (per-t granularity)
    if (tid == 0) {
        volatile int* flag = &g_done[gp][t];
        while (atomicAdd((int*)flag, 0) < TILES_PER_T) __nanosleep(128);
        __threadfence();
    }
    __syncthreads();

    int wm = wid & 1, wn = wid >> 1;     // 2x2 warp grid

    const __half *A, *B;
    if (gp == 0)      { A = g_Gh;  B = g_Gh;  }
    else if (gp == 1) { A = g_G2h; B = g_Gh;  }
    else              { A = g_Qh;  B = g_G3h; }

    float cf[4][8][4];
#pragma unroll
    for (int mt = 0; mt < 4; mt++)
#pragma unroll
        for (int nf = 0; nf < 8; nf++)
#pragma unroll
            for (int e = 0; e < 4; e++) cf[mt][nf][e] = 0.f;

    uint32_t xorv  = (uint32_t)((l & 7) << 4);
    uint32_t a_row = (uint32_t)(wm * 64 + (l & 15));
    uint32_t a_kb  = (uint32_t)((l >> 4) << 4);
    uint32_t b_k0  = (uint32_t)(l & 15);
    uint32_t b_nb  = (uint32_t)(wn * 128 + ((l >> 4) << 4));   // bytes

    auto load_stage = [&](int s, int kk) {
        uint32_t stA = smem_base + s * STAGE_BYTES;
        uint32_t stB = stA + BM * 128;
        const __half* Ab = A + baseT + (size_t)m0 * NN + kk;
        const __half* Bb = B + baseT + (size_t)kk * NN + n0;
#pragma unroll
        for (int q = 0; q < 8; q++) {            // A: 1024 16B chunks
            int id = tid + q * 128;
            int row = id >> 3, kc = id & 7;
            cpasync16(stA + ((uint32_t)(row << 7) + (((uint32_t)(kc << 4)) ^ ((uint32_t)(row & 7) << 4))),
                      Ab + (size_t)row * NN + kc * 8);
        }
#pragma unroll
        for (int q = 0; q < 8; q++) {            // B: 1024 16B chunks
            int id = tid + q * 128;
            int k = id >> 4, nc = id & 15;
            cpasync16(stB + ((uint32_t)(k << 8) + (((uint32_t)(nc << 4)) ^ ((uint32_t)(k & 7) << 4))),
                      Bb + (size_t)k * NN + nc * 8);
        }
        asm volatile("cp.async.commit_group;\n");
    };

    uint32_t af[2][4][4], bf[2][4][4];

    auto load_frags = [&](int buf, uint32_t stA, uint32_t stB, int ks) {
#pragma unroll
        for (int mt = 0; mt < 4; mt++)
            ldsm4(af[buf][mt], stA + ((a_row + mt * 16) << 7) + ((a_kb + ks * 32) ^ xorv));
#pragma unroll
        for (int np = 0; np < 4; np++)
            ldsm4t(bf[buf][np], stB + ((b_k0 + ks * 16) << 8) + ((b_nb + np * 32) ^ xorv));
    };
    auto mma_frags = [&](int buf) {
#pragma unroll
        for (int mt = 0; mt < 4; mt++)
#pragma unroll
            for (int np = 0; np < 4; np++) {
                mma16816(cf[mt][np * 2],     af[buf][mt], bf[buf][np][0], bf[buf][np][1]);
                mma16816(cf[mt][np * 2 + 1], af[buf][mt], bf[buf][np][2], bf[buf][np][3]);
            }
    };

    load_stage(0, 0);
    load_stage(1, BK);

#pragma unroll 1
    for (int ch = 0; ch < KCH; ch++) {
        if (ch + 1 < KCH) asm volatile("cp.async.wait_group 1;\n");
        else              asm volatile("cp.async.wait_group 0;\n");
        __syncthreads();

        uint32_t stA = smem_base + (ch % 3) * STAGE_BYTES;
        uint32_t stB = stA + BM * 128;

        load_frags(0, stA, stB, 0);
        load_frags(1, stA, stB, 1);   // prefetch ks1
        mma_frags(0);                 // ks0
        if (ch + 2 < KCH) load_stage((ch + 2) % 3, (ch + 2) * BK);
        load_frags(0, stA, stB, 2);   // prefetch ks2
        mma_frags(1);                 // ks1
        load_frags(1, stA, stB, 3);   // prefetch ks3
        mma_frags(0);                 // ks2
        mma_frags(1);                 // ks3
    }
    __syncthreads();

    // stage accumulators through smem (stride 132 floats)
#pragma unroll
    for (int mt = 0; mt < 4; mt++) {
        int r0 = wm * 64 + mt * 16 + (l >> 2);
#pragma unroll
        for (int nf = 0; nf < 8; nf++) {
            int col = wn * 64 + nf * 8 + (l & 3) * 2;
            stg[r0 * 132 + col]           = cf[mt][nf][0];
            stg[r0 * 132 + col + 1]       = cf[mt][nf][1];
            stg[(r0 + 8) * 132 + col]     = cf[mt][nf][2];
            stg[(r0 + 8) * 132 + col + 1] = cf[mt][nf][3];
        }
    }
    __syncthreads();

    float a0c = g_coef[t][0], a1c = g_coef[t][1], a2c = g_coef[t][2];
    float a3c = g_coef[t][3], a4c = g_coef[t][4], a5c = g_coef[t][5];

#pragma unroll 1
    for (int pass = 0; pass < 32; pass++) {
        int r = pass * 4 + (tid >> 5);
        int col = (tid & 31) * 4;
        int gi = m0 + r;
        int dj = gi - (n0 + col);          // 0..3 => diagonal hit
        size_t o = baseT + (size_t)gi * NN + (n0 + col);
        float v0 = stg[r * 132 + col],     v1 = stg[r * 132 + col + 1];
        float v2 = stg[r * 132 + col + 2], v3 = stg[r * 132 + col + 3];

        if (gp == 0) {
            uint2 gv = *reinterpret_cast<const uint2*>(g_Gh + o);
            __half2 g01 = *reinterpret_cast<__half2*>(&gv.x);
            __half2 g23 = *reinterpret_cast<__half2*>(&gv.y);
            float q0 = a5c * v0 + a4c * __low2float(g01)  + (dj == 0 ? a3c : 0.f);
            float q1 = a5c * v1 + a4c * __high2float(g01) + (dj == 1 ? a3c : 0.f);
            float q2 = a5c * v2 + a4c * __low2float(g23)  + (dj == 2 ? a3c : 0.f);
            float q3 = a5c * v3 + a4c * __high2float(g23) + (dj == 3 ? a3c : 0.f);
            union { uint2 u; __half2 h[2]; } p, q;
            p.h[0] = __floats2half2_rn(v0, v1); p.h[1] = __floats2half2_rn(v2, v3);
            q.h[0] = __floats2half2_rn(q0, q1); q.h[1] = __floats2half2_rn(q2, q3);
            *reinterpret_cast<uint2*>(g_G2h + o) = p.u;
            *reinterpret_cast<uint2*>(g_Qh + o)  = q.u;
        } else if (gp == 1) {
            union { uint2 u; __half2 h[2]; } p;
            p.h[0] = __floats2half2_rn(v0, v1); p.h[1] = __floats2half2_rn(v2, v3);
            *reinterpret_cast<uint2*>(g_G3h + o) = p.u;
        } else {
            uint2 gv = *reinterpret_cast<const uint2*>(g_Gh + o);
            uint2 g2 = *reinterpret_cast<const uint2*>(g_G2h + o);
            __half2 g01 = *reinterpret_cast<__half2*>(&gv.x);
            __half2 g23 = *reinterpret_cast<__half2*>(&gv.y);
            __half2 h01 = *reinterpret_cast<__half2*>(&g2.x);
            __half2 h23 = *reinterpret_cast<__half2*>(&g2.y);
            float4 rr;
            rr.x = v0 + a2c * __low2float(h01)  + a1c * __low2float(g01)  + (dj == 0 ? a0c : 0.f);
            rr.y = v1 + a2c * __high2float(h01) + a1c * __high2float(g01) + (dj == 1 ? a0c : 0.f);
            rr.z = v2 + a2c * __low2float(h23)  + a1c * __low2float(g23)  + (dj == 2 ? a0c : 0.f);
            rr.w = v3 + a2c * __high2float(h23) + a1c * __high2float(g23) + (dj == 3 ? a0c : 0.f);
            *reinterpret_cast<float4*>(g_acc + o) = rr;
        }
    }

    // signal completion
    __syncthreads();
    if (tid == 0) {
        __threadfence();
        atomicAdd(&g_done[gp + 1][t], 1);
    }
}

extern "C" void kernel_launch(void* const* d_in, const int* in_sizes, int n_in,
                              void* d_out, int out_size) {
    const float* x      = (const float*)d_in[0];
    const float* weight = (const float*)d_in[1];
    const float* gamma  = (const float*)d_in[2];
    const float* beta   = (const float*)d_in[3];
    float* out = (float*)d_out;

    cudaFuncSetAttribute(fused_kernel,
                         cudaFuncAttributeMaxDynamicSharedMemorySize, SMEM_DYN);

    coef_kernel<<<1, 64>>>(weight);
    fused_kernel<<<5 * CTAS_PER_PHASE, 128, SMEM_DYN>>>(x, gamma, beta, out);
}

// round 13
// speedup vs baseline: 1.0034x; 1.0034x over previous
#include <cuda_runtime.h>
#include <cuda_fp16.h>
#include <cstdint>

#define NN 2048
#define NT 10
#define KK 5
constexpr float LN_EPS = 1e-5f;

// GEMM tiling: CTA 128x128, BK=64, 4 warps (2x2), warp tile 64x64, 3 stages
// 2 CTAs/SM. 3 GEMM phases + LN fused in one launch, row-block-granular deps.
#define BM 128
#define BN 128
#define BK 64
#define KCH (NN / BK)                          // 32
#define STAGE_BYTES (BM * 128 + BK * 256)      // A 16KB + B 16KB = 32KB
#define SMEM_DYN (3 * STAGE_BYTES + 1024)      // 99328
#define TILES_PER_T 256                        // 16x16
#define CTAS_PER_PHASE (NT * TILES_PER_T)      // 2560
// phases: 0=G2, 1=G3, 2=R, 3=LN

// Scratch (__device__ globals; allocation-free rule)
__device__ __half g_Gh [(size_t)NT * NN * NN];  // G_norm
__device__ __half g_G2h[(size_t)NT * NN * NN];  // G^2
__device__ __half g_G3h[(size_t)NT * NN * NN];  // G^3
__device__ __half g_Qh [(size_t)NT * NN * NN];  // Q = a5 G^2 + a4 G + a3 I
__device__ float  g_acc[(size_t)NT * NN * NN];  // pre-LN accumulator (fp32)
__device__ float  g_coef[NT][6];
__device__ int    g_c0[NT][16];                 // phase0 per-(t,mb) counters
__device__ int    g_c1[NT];                     // phase1 per-t counter
__device__ int    g_c2[NT][16];                 // phase2 per-(t,mb) counters

__device__ __forceinline__ float clip01(float v) { return fminf(fmaxf(v, 0.f), 1.f); }

__device__ __forceinline__ void cpasync16(uint32_t s, const void* g) {
    asm volatile("cp.async.cg.shared.global [%0], [%1], 16;\n" :: "r"(s), "l"(g));
}
__device__ __forceinline__ void ldsm4(uint32_t* r, uint32_t addr) {
    asm volatile("ldmatrix.sync.aligned.m8n8.x4.shared.b16 {%0,%1,%2,%3}, [%4];"
                 : "=r"(r[0]), "=r"(r[1]), "=r"(r[2]), "=r"(r[3]) : "r"(addr));
}
__device__ __forceinline__ void ldsm4t(uint32_t* r, uint32_t addr) {
    asm volatile("ldmatrix.sync.aligned.m8n8.x4.trans.shared.b16 {%0,%1,%2,%3}, [%4];"
                 : "=r"(r[0]), "=r"(r[1]), "=r"(r[2]), "=r"(r[3]) : "r"(addr));
}
__device__ __forceinline__ void mma16816(float* c, const uint32_t* a,
                                         uint32_t b0, uint32_t b1) {
    asm volatile("mma.sync.aligned.m16n8k16.row.col.f32.f16.f16.f32 "
                 "{%0,%1,%2,%3}, {%4,%5,%6,%7}, {%8,%9}, {%0,%1,%2,%3};"
                 : "+f"(c[0]), "+f"(c[1]), "+f"(c[2]), "+f"(c[3])
                 : "r"(a[0]), "r"(a[1]), "r"(a[2]), "r"(a[3]), "r"(b0), "r"(b1));
}

__device__ __forceinline__ void wait_flag(volatile int* flag, int target) {
    while (atomicAdd((int*)flag, 0) < target) __nanosleep(128);
    __threadfence();
}

// -------------------------------------------------------------------------
// coef: per t, polynomial coefficients; zero dependency counters
// -------------------------------------------------------------------------
__global__ void coef_kernel(const float* __restrict__ w) {
    int id = threadIdx.x;
    if (id < NT * 16) { ((int*)g_c0)[id] = 0; ((int*)g_c2)[id] = 0; }
    if (id < NT) g_c1[id] = 0;
    int t = id;
    if (t >= NT) return;
    float c[6] = {1.f, 0.f, 0.f, 0.f, 0.f, 0.f};
    float a[6] = {0.f, 0.f, 0.f, 0.f, 0.f, 0.f};
    for (int k = 0; k < KK; k++) {
        float wk = clip01(w[t * KK + k]);
        float nc[6];
        nc[0] = 1.f - wk;
#pragma unroll
        for (int m = 1; m < 6; m++) nc[m] = wk * c[m - 1];
#pragma unroll
        for (int m = 0; m < 6; m++) { c[m] = nc[m]; a[m] += nc[m]; }
    }
#pragma unroll
    for (int m = 0; m < 6; m++) g_coef[t][m] = a[m];
}

// -------------------------------------------------------------------------
// prep: per (t,i) row — degree + row-normalize -> g_Gh (fp16)
// -------------------------------------------------------------------------
__global__ __launch_bounds__(256) void prep_kernel(const float* __restrict__ x) {
    int row = blockIdx.x;
    int t = row / NN, i = row - t * NN;
    const float4* xr = reinterpret_cast<const float4*>(x + ((size_t)i * NT + t) * NN);

    float4 v[2];
    float s = 0.f;
#pragma unroll
    for (int q = 0; q < 2; q++) {
        v[q] = xr[threadIdx.x + q * 256];
        s += v[q].x + v[q].y + v[q].z + v[q].w;
    }
    __shared__ float red[8];
    for (int o = 16; o; o >>= 1) s += __shfl_down_sync(0xffffffffu, s, o);
    if ((threadIdx.x & 31) == 0) red[threadIdx.x >> 5] = s;
    __syncthreads();
    if (threadIdx.x == 0) {
        float tt = 0.f;
#pragma unroll
        for (int q = 0; q < 8; q++) tt += red[q];
        red[0] = tt;
    }
    __syncthreads();
    float inv = 1.f / (red[0] + 1e-8f);
    size_t base = ((size_t)t * NN + i) * NN;
#pragma unroll
    for (int q = 0; q < 2; q++) {
        int j0 = (threadIdx.x + q * 256) * 4;
        *reinterpret_cast<__half2*>(&g_Gh[base + j0]) =
            __floats2half2_rn(v[q].x * inv, v[q].y * inv);
        *reinterpret_cast<__half2*>(&g_Gh[base + j0 + 2]) =
            __floats2half2_rn(v[q].z * inv, v[q].w * inv);
    }
}

// -------------------------------------------------------------------------
// Fused launch: phases 0..2 GEMM chain, phase 3 LayerNorm (tail overlap).
//   phase 0: G2 = G*G    (writes G2h, Qh)  -> c0[t][mb]
//   phase 1: G3 = G2*G   (writes G3h)      -> c1[t]      waits c0[t][mb]==16
//   phase 2: R  = Q*G3   (writes g_acc)    -> c2[t][mb]  waits c1[t]==256
//   phase 3: LN rows     (writes out)                   waits c2[t][mb]==16
// -------------------------------------------------------------------------
__global__ __launch_bounds__(128, 2) void fused_kernel(
    const float* __restrict__ gamma,
    const float* __restrict__ beta,
    float* __restrict__ out
) {
    extern __shared__ unsigned char dsm_raw[];
    uint32_t dsm = (uint32_t)__cvta_generic_to_shared(dsm_raw);
    uint32_t smem_base = (dsm + 1023) & ~1023u;
    float* stg = reinterpret_cast<float*>(dsm_raw + (smem_base - dsm));

    __shared__ float red[2][4];

    int tid = threadIdx.x;
    int l = tid & 31, wid = tid >> 5;

    int bid = blockIdx.x;
    int phase = bid / CTAS_PER_PHASE;
    int rem = bid - phase * CTAS_PER_PHASE;
    int t = rem / TILES_PER_T;
    int sub = rem - t * TILES_PER_T;
    size_t baseT = (size_t)t * NN * NN;

    // ===================== phase 3: LayerNorm (8 rows per CTA) ===========
    if (phase == 3) {
        if (tid == 0) wait_flag(&g_c2[t][sub >> 4], 16);
        __syncthreads();
#pragma unroll 1
        for (int rr = 0; rr < 8; rr++) {
            int i = sub * 8 + rr;
            const float4* a = reinterpret_cast<const float4*>(
                g_acc + baseT + (size_t)i * NN);
            float4 v[4];
            float s = 0.f, ss = 0.f;
#pragma unroll
            for (int q = 0; q < 4; q++) {
                v[q] = a[tid + q * 128];
                s  += v[q].x + v[q].y + v[q].z + v[q].w;
                ss += v[q].x * v[q].x + v[q].y * v[q].y
                    + v[q].z * v[q].z + v[q].w * v[q].w;
            }
            for (int o = 16; o; o >>= 1) {
                s  += __shfl_down_sync(0xffffffffu, s, o);
                ss += __shfl_down_sync(0xffffffffu, ss, o);
            }
            if (l == 0) { red[0][wid] = s; red[1][wid] = ss; }
            __syncthreads();
            float sum  = red[0][0] + red[0][1] + red[0][2] + red[0][3];
            float sumq = red[1][0] + red[1][1] + red[1][2] + red[1][3];
            float mu = sum * (1.f / NN);
            float var = sumq * (1.f / NN) - mu * mu;
            float rstd = rsqrtf(var + LN_EPS);
            float4* o4 = reinterpret_cast<float4*>(out + ((size_t)i * NT + t) * NN);
            const float4* gm = reinterpret_cast<const float4*>(gamma);
            const float4* bt = reinterpret_cast<const float4*>(beta);
#pragma unroll
            for (int q = 0; q < 4; q++) {
                int idx = tid + q * 128;
                float4 g = gm[idx], b = bt[idx];
                float4 r;
                r.x = (v[q].x - mu) * rstd * g.x + b.x;
                r.y = (v[q].y - mu) * rstd * g.y + b.y;
                r.z = (v[q].z - mu) * rstd * g.z + b.z;
                r.w = (v[q].w - mu) * rstd * g.w + b.w;
                o4[idx] = r;
            }
            __syncthreads();
        }
        return;
    }

    // ===================== phases 0..2: GEMM chain =======================
    int gp = phase;                     // 0: G2=G*G, 1: G3=G2*G, 2: R=Q*G3
    int mb = sub >> 4;
    int m0 = mb * BM;
    int n0 = (sub & 15) * BN;

    // dependency waits (row-block granular where possible)
    if (tid == 0) {
        if (gp == 1)      wait_flag(&g_c0[t][mb], 16);   // A = G2 rows mb
        else if (gp == 2) wait_flag(&g_c1[t], TILES_PER_T); // B = full G3[t]
    }
    __syncthreads();

    int wm = wid & 1, wn = wid >> 1;     // 2x2 warp grid

    const __half *A, *B;
    if (gp == 0)      { A = g_Gh;  B = g_Gh;  }
    else if (gp == 1) { A = g_G2h; B = g_Gh;  }
    else              { A = g_Qh;  B = g_G3h; }

    float cf[4][8][4];
#pragma unroll
    for (int mt = 0; mt < 4; mt++)
#pragma unroll
        for (int nf = 0; nf < 8; nf++)
#pragma unroll
            for (int e = 0; e < 4; e++) cf[mt][nf][e] = 0.f;

    uint32_t xorv  = (uint32_t)((l & 7) << 4);
    uint32_t a_row = (uint32_t)(wm * 64 + (l & 15));
    uint32_t a_kb  = (uint32_t)((l >> 4) << 4);
    uint32_t b_k0  = (uint32_t)(l & 15);
    uint32_t b_nb  = (uint32_t)(wn * 128 + ((l >> 4) << 4));   // bytes

    auto load_stage = [&](int s, int kk) {
        uint32_t stA = smem_base + s * STAGE_BYTES;
        uint32_t stB = stA + BM * 128;
        const __half* Ab = A + baseT + (size_t)m0 * NN + kk;
        const __half* Bb = B + baseT + (size_t)kk * NN + n0;
#pragma unroll
        for (int q = 0; q < 8; q++) {            // A: 1024 16B chunks
            int id = tid + q * 128;
            int row = id >> 3, kc = id & 7;
            cpasync16(stA + ((uint32_t)(row << 7) + (((uint32_t)(kc << 4)) ^ ((uint32_t)(row & 7) << 4))),
                      Ab + (size_t)row * NN + kc * 8);
        }
#pragma unroll
        for (int q = 0; q < 8; q++) {            // B: 1024 16B chunks
            int id = tid + q * 128;
            int k = id >> 4, nc = id & 15;
            cpasync16(stB + ((uint32_t)(k << 8) + (((uint32_t)(nc << 4)) ^ ((uint32_t)(k & 7) << 4))),
                      Bb + (size_t)k * NN + nc * 8);
        }
        asm volatile("cp.async.commit_group;\n");
    };

    uint32_t af[2][4][4], bf[2][4][4];

    auto load_frags = [&](int buf, uint32_t stA, uint32_t stB, int ks) {
#pragma unroll
        for (int mt = 0; mt < 4; mt++)
            ldsm4(af[buf][mt], stA + ((a_row + mt * 16) << 7) + ((a_kb + ks * 32) ^ xorv));
#pragma unroll
        for (int np = 0; np < 4; np++)
            ldsm4t(bf[buf][np], stB + ((b_k0 + ks * 16) << 8) + ((b_nb + np * 32) ^ xorv));
    };
    auto mma_frags = [&](int buf) {
#pragma unroll
        for (int mt = 0; mt < 4; mt++)
#pragma unroll
            for (int np = 0; np < 4; np++) {
                mma16816(cf[mt][np * 2],     af[buf][mt], bf[buf][np][0], bf[buf][np][1]);
                mma16816(cf[mt][np * 2 + 1], af[buf][mt], bf[buf][np][2], bf[buf][np][3]);
            }
    };

    load_stage(0, 0);
    load_stage(1, BK);

#pragma unroll 1
    for (int ch = 0; ch < KCH; ch++) {
        if (ch + 1 < KCH) asm volatile("cp.async.wait_group 1;\n");
        else              asm volatile("cp.async.wait_group 0;\n");
        __syncthreads();

        uint32_t stA = smem_base + (ch % 3) * STAGE_BYTES;
        uint32_t stB = stA + BM * 128;

        load_frags(0, stA, stB, 0);
        load_frags(1, stA, stB, 1);   // prefetch ks1
        mma_frags(0);                 // ks0
        if (ch + 2 < KCH) load_stage((ch + 2) % 3, (ch + 2) * BK);
        load_frags(0, stA, stB, 2);   // prefetch ks2
        mma_frags(1);                 // ks1
        load_frags(1, stA, stB, 3);   // prefetch ks3
        mma_frags(0);                 // ks2
        mma_frags(1);                 // ks3
    }
    __syncthreads();

    // stage accumulators through smem (stride 132 floats)
#pragma unroll
    for (int mt = 0; mt < 4; mt++) {
        int r0 = wm * 64 + mt * 16 + (l >> 2);
#pragma unroll
        for (int nf = 0; nf < 8; nf++) {
            int col = wn * 64 + nf * 8 + (l & 3) * 2;
            stg[r0 * 132 + col]           = cf[mt][nf][0];
            stg[r0 * 132 + col + 1]       = cf[mt][nf][1];
            stg[(r0 + 8) * 132 + col]     = cf[mt][nf][2];
            stg[(r0 + 8) * 132 + col + 1] = cf[mt][nf][3];
        }
    }
    __syncthreads();

    float a0c = g_coef[t][0], a1c = g_coef[t][1], a2c = g_coef[t][2];
    float a3c = g_coef[t][3], a4c = g_coef[t][4], a5c = g_coef[t][5];

#pragma unroll 1
    for (int pass = 0; pass < 32; pass++) {
        int r = pass * 4 + (tid >> 5);
        int col = (tid & 31) * 4;
        int gi = m0 + r;
        int dj = gi - (n0 + col);          // 0..3 => diagonal hit
        size_t o = baseT + (size_t)gi * NN + (n0 + col);
        float v0 = stg[r * 132 + col],     v1 = stg[r * 132 + col + 1];
        float v2 = stg[r * 132 + col + 2], v3 = stg[r * 132 + col + 3];

        if (gp == 0) {
            uint2 gv = *reinterpret_cast<const uint2*>(g_Gh + o);
            __half2 g01 = *reinterpret_cast<__half2*>(&gv.x);
            __half2 g23 = *reinterpret_cast<__half2*>(&gv.y);
            float q0 = a5c * v0 + a4c * __low2float(g01)  + (dj == 0 ? a3c : 0.f);
            float q1 = a5c * v1 + a4c * __high2float(g01) + (dj == 1 ? a3c : 0.f);
            float q2 = a5c * v2 + a4c * __low2float(g23)  + (dj == 2 ? a3c : 0.f);
            float q3 = a5c * v3 + a4c * __high2float(g23) + (dj == 3 ? a3c : 0.f);
            union { uint2 u; __half2 h[2]; } p, q;
            p.h[0] = __floats2half2_rn(v0, v1); p.h[1] = __floats2half2_rn(v2, v3);
            q.h[0] = __floats2half2_rn(q0, q1); q.h[1] = __floats2half2_rn(q2, q3);
            *reinterpret_cast<uint2*>(g_G2h + o) = p.u;
            *reinterpret_cast<uint2*>(g_Qh + o)  = q.u;
        } else if (gp == 1) {
            union { uint2 u; __half2 h[2]; } p;
            p.h[0] = __floats2half2_rn(v0, v1); p.h[1] = __floats2half2_rn(v2, v3);
            *reinterpret_cast<uint2*>(g_G3h + o) = p.u;
        } else {
            uint2 gv = *reinterpret_cast<const uint2*>(g_Gh + o);
            uint2 g2 = *reinterpret_cast<const uint2*>(g_G2h + o);
            __half2 g01 = *reinterpret_cast<__half2*>(&gv.x);
            __half2 g23 = *reinterpret_cast<__half2*>(&gv.y);
            __half2 h01 = *reinterpret_cast<__half2*>(&g2.x);
            __half2 h23 = *reinterpret_cast<__half2*>(&g2.y);
            float4 rr;
            rr.x = v0 + a2c * __low2float(h01)  + a1c * __low2float(g01)  + (dj == 0 ? a0c : 0.f);
            rr.y = v1 + a2c * __high2float(h01) + a1c * __high2float(g01) + (dj == 1 ? a0c : 0.f);
            rr.z = v2 + a2c * __low2float(h23)  + a1c * __low2float(g23)  + (dj == 2 ? a0c : 0.f);
            rr.w = v3 + a2c * __high2float(h23) + a1c * __high2float(g23) + (dj == 3 ? a0c : 0.f);
            *reinterpret_cast<float4*>(g_acc + o) = rr;
        }
    }

    // signal completion
    __syncthreads();
    if (tid == 0) {
        __threadfence();
        if (gp == 0)      atomicAdd(&g_c0[t][mb], 1);
        else if (gp == 1) atomicAdd(&g_c1[t], 1);
        else              atomicAdd(&g_c2[t][mb], 1);
    }
}

extern "C" void kernel_launch(void* const* d_in, const int* in_sizes, int n_in,
                              void* d_out, int out_size) {
    const float* x      = (const float*)d_in[0];
    const float* weight = (const float*)d_in[1];
    const float* gamma  = (const float*)d_in[2];
    const float* beta   = (const float*)d_in[3];
    float* out = (float*)d_out;

    cudaFuncSetAttribute(fused_kernel,
                         cudaFuncAttributeMaxDynamicSharedMemorySize, SMEM_DYN);

    coef_kernel<<<1, 192>>>(weight);
    prep_kernel<<<NT * NN, 256>>>(x);

    fused_kernel<<<4 * CTAS_PER_PHASE, 128, SMEM_DYN>>>(gamma, beta, out);
}

// round 14
// speedup vs baseline: 1.0310x; 1.0275x over previous
#include <cuda_runtime.h>
#include <cuda_fp16.h>
#include <cstdint>

#define NN 2048
#define NT 10
#define KK 5
constexpr float LN_EPS = 1e-5f;

// GEMM tiling: CTA 128x128, BK=64, 4 warps (2x2), warp tile 64x64, 3 stages
// 2 CTAs/SM. 3 GEMM phases fused in one launch, row-block-granular deps for
// phase 1. prep/LN run as dedicated high-occupancy kernels.
#define BM 128
#define BN 128
#define BK 64
#define KCH (NN / BK)                          // 32
#define STAGE_BYTES (BM * 128 + BK * 256)      // A 16KB + B 16KB = 32KB
#define SMEM_DYN (3 * STAGE_BYTES + 1024)      // 99328
#define TILES_PER_T 256                        // 16x16
#define CTAS_PER_PHASE (NT * TILES_PER_T)      // 2560
// phases: 0=G2, 1=G3, 2=R

// Scratch (__device__ globals; allocation-free rule)
__device__ __half g_Gh [(size_t)NT * NN * NN];  // G_norm
__device__ __half g_G2h[(size_t)NT * NN * NN];  // G^2
__device__ __half g_G3h[(size_t)NT * NN * NN];  // G^3
__device__ __half g_Qh [(size_t)NT * NN * NN];  // Q = a5 G^2 + a4 G + a3 I
__device__ float  g_acc[(size_t)NT * NN * NN];  // pre-LN accumulator (fp32)
__device__ float  g_coef[NT][6];
__device__ int    g_c0[NT][16];                 // phase0 per-(t,mb) counters
__device__ int    g_c1[NT];                     // phase1 per-t counter

__device__ __forceinline__ float clip01(float v) { return fminf(fmaxf(v, 0.f), 1.f); }

__device__ __forceinline__ void cpasync16(uint32_t s, const void* g) {
    asm volatile("cp.async.cg.shared.global [%0], [%1], 16;\n" :: "r"(s), "l"(g));
}
__device__ __forceinline__ void ldsm4(uint32_t* r, uint32_t addr) {
    asm volatile("ldmatrix.sync.aligned.m8n8.x4.shared.b16 {%0,%1,%2,%3}, [%4];"
                 : "=r"(r[0]), "=r"(r[1]), "=r"(r[2]), "=r"(r[3]) : "r"(addr));
}
__device__ __forceinline__ void ldsm4t(uint32_t* r, uint32_t addr) {
    asm volatile("ldmatrix.sync.aligned.m8n8.x4.trans.shared.b16 {%0,%1,%2,%3}, [%4];"
                 : "=r"(r[0]), "=r"(r[1]), "=r"(r[2]), "=r"(r[3]) : "r"(addr));
}
__device__ __forceinline__ void mma16816(float* c, const uint32_t* a,
                                         uint32_t b0, uint32_t b1) {
    asm volatile("mma.sync.aligned.m16n8k16.row.col.f32.f16.f16.f32 "
                 "{%0,%1,%2,%3}, {%4,%5,%6,%7}, {%8,%9}, {%0,%1,%2,%3};"
                 : "+f"(c[0]), "+f"(c[1]), "+f"(c[2]), "+f"(c[3])
                 : "r"(a[0]), "r"(a[1]), "r"(a[2]), "r"(a[3]), "r"(b0), "r"(b1));
}

__device__ __forceinline__ void wait_flag(volatile int* flag, int target) {
    while (atomicAdd((int*)flag, 0) < target) __nanosleep(128);
    __threadfence();
}

// -------------------------------------------------------------------------
// prep: per (t,i) row — degree + row-normalize -> g_Gh (fp16).
// Block 0 additionally computes polynomial coefficients + zeroes counters
// (visible to the fused kernel via the launch boundary).
// -------------------------------------------------------------------------
__global__ __launch_bounds__(256) void prep_kernel(const float* __restrict__ x,
                                                   const float* __restrict__ w) {
    if (blockIdx.x == 0) {
        int id = threadIdx.x;
        if (id < NT * 16) ((int*)g_c0)[id] = 0;
        if (id < NT) g_c1[id] = 0;
        if (id < NT) {
            int t = id;
            float c[6] = {1.f, 0.f, 0.f, 0.f, 0.f, 0.f};
            float a[6] = {0.f, 0.f, 0.f, 0.f, 0.f, 0.f};
            for (int k = 0; k < KK; k++) {
                float wk = clip01(w[t * KK + k]);
                float nc[6];
                nc[0] = 1.f - wk;
#pragma unroll
                for (int m = 1; m < 6; m++) nc[m] = wk * c[m - 1];
#pragma unroll
                for (int m = 0; m < 6; m++) { c[m] = nc[m]; a[m] += nc[m]; }
            }
#pragma unroll
            for (int m = 0; m < 6; m++) g_coef[t][m] = a[m];
        }
    }

    int row = blockIdx.x;
    int t = row / NN, i = row - t * NN;
    const float4* xr = reinterpret_cast<const float4*>(x + ((size_t)i * NT + t) * NN);

    float4 v[2];
    float s = 0.f;
#pragma unroll
    for (int q = 0; q < 2; q++) {
        v[q] = xr[threadIdx.x + q * 256];
        s += v[q].x + v[q].y + v[q].z + v[q].w;
    }
    __shared__ float red[8];
    for (int o = 16; o; o >>= 1) s += __shfl_down_sync(0xffffffffu, s, o);
    if ((threadIdx.x & 31) == 0) red[threadIdx.x >> 5] = s;
    __syncthreads();
    if (threadIdx.x == 0) {
        float tt = 0.f;
#pragma unroll
        for (int q = 0; q < 8; q++) tt += red[q];
        red[0] = tt;
    }
    __syncthreads();
    float inv = 1.f / (red[0] + 1e-8f);
    size_t base = ((size_t)t * NN + i) * NN;
#pragma unroll
    for (int q = 0; q < 2; q++) {
        int j0 = (threadIdx.x + q * 256) * 4;
        *reinterpret_cast<__half2*>(&g_Gh[base + j0]) =
            __floats2half2_rn(v[q].x * inv, v[q].y * inv);
        *reinterpret_cast<__half2*>(&g_Gh[base + j0 + 2]) =
            __floats2half2_rn(v[q].z * inv, v[q].w * inv);
    }
}

// -------------------------------------------------------------------------
// Fused 3-phase GEMM, one launch (grid 3*2560):
//   phase 0: G2 = G*G    (writes G2h, Qh)  -> c0[t][mb]
//   phase 1: G3 = G2*G   (writes G3h)      -> c1[t]   waits c0[t][mb]==16
//   phase 2: R  = Q*G3   (writes g_acc)               waits c1[t]==256
// -------------------------------------------------------------------------
__global__ __launch_bounds__(128, 2) void gemm_fused_kernel() {
    extern __shared__ unsigned char dsm_raw[];
    uint32_t dsm = (uint32_t)__cvta_generic_to_shared(dsm_raw);
    uint32_t smem_base = (dsm + 1023) & ~1023u;
    float* stg = reinterpret_cast<float*>(dsm_raw + (smem_base - dsm));

    int tid = threadIdx.x;
    int l = tid & 31, wid = tid >> 5;
    int wm = wid & 1, wn = wid >> 1;     // 2x2 warp grid

    int bid = blockIdx.x;
    int phase = bid / CTAS_PER_PHASE;
    int rem = bid - phase * CTAS_PER_PHASE;
    int t = rem / TILES_PER_T;
    int sub = rem - t * TILES_PER_T;
    int mb = sub >> 4;
    int m0 = mb * BM;
    int n0 = (sub & 15) * BN;
    size_t baseT = (size_t)t * NN * NN;

    // dependency waits (row-block granular for phase 1)
    if (tid == 0) {
        if (phase == 1)      wait_flag(&g_c0[t][mb], 16);       // A = G2 rows mb
        else if (phase == 2) wait_flag(&g_c1[t], TILES_PER_T);  // B = full G3[t]
    }
    __syncthreads();

    const __half *A, *B;
    if (phase == 0)      { A = g_Gh;  B = g_Gh;  }
    else if (phase == 1) { A = g_G2h; B = g_Gh;  }
    else                 { A = g_Qh;  B = g_G3h; }

    float cf[4][8][4];
#pragma unroll
    for (int mt = 0; mt < 4; mt++)
#pragma unroll
        for (int nf = 0; nf < 8; nf++)
#pragma unroll
            for (int e = 0; e < 4; e++) cf[mt][nf][e] = 0.f;

    uint32_t xorv  = (uint32_t)((l & 7) << 4);
    uint32_t a_row = (uint32_t)(wm * 64 + (l & 15));
    uint32_t a_kb  = (uint32_t)((l >> 4) << 4);
    uint32_t b_k0  = (uint32_t)(l & 15);
    uint32_t b_nb  = (uint32_t)(wn * 128 + ((l >> 4) << 4));   // bytes

    auto load_stage = [&](int s, int kk) {
        uint32_t stA = smem_base + s * STAGE_BYTES;
        uint32_t stB = stA + BM * 128;
        const __half* Ab = A + baseT + (size_t)m0 * NN + kk;
        const __half* Bb = B + baseT + (size_t)kk * NN + n0;
#pragma unroll
        for (int q = 0; q < 8; q++) {            // A: 1024 16B chunks
            int id = tid + q * 128;
            int row = id >> 3, kc = id & 7;
            cpasync16(stA + ((uint32_t)(row << 7) + (((uint32_t)(kc << 4)) ^ ((uint32_t)(row & 7) << 4))),
                      Ab + (size_t)row * NN + kc * 8);
        }
#pragma unroll
        for (int q = 0; q < 8; q++) {            // B: 1024 16B chunks
            int id = tid + q * 128;
            int k = id >> 4, nc = id & 15;
            cpasync16(stB + ((uint32_t)(k << 8) + (((uint32_t)(nc << 4)) ^ ((uint32_t)(k & 7) << 4))),
                      Bb + (size_t)k * NN + nc * 8);
        }
        asm volatile("cp.async.commit_group;\n");
    };

    uint32_t af[2][4][4], bf[2][4][4];

    auto load_frags = [&](int buf, uint32_t stA, uint32_t stB, int ks) {
#pragma unroll
        for (int mt = 0; mt < 4; mt++)
            ldsm4(af[buf][mt], stA + ((a_row + mt * 16) << 7) + ((a_kb + ks * 32) ^ xorv));
#pragma unroll
        for (int np = 0; np < 4; np++)
            ldsm4t(bf[buf][np], stB + ((b_k0 + ks * 16) << 8) + ((b_nb + np * 32) ^ xorv));
    };
    auto mma_frags = [&](int buf) {
#pragma unroll
        for (int mt = 0; mt < 4; mt++)
#pragma unroll
            for (int np = 0; np < 4; np++) {
                mma16816(cf[mt][np * 2],     af[buf][mt], bf[buf][np][0], bf[buf][np][1]);
                mma16816(cf[mt][np * 2 + 1], af[buf][mt], bf[buf][np][2], bf[buf][np][3]);
            }
    };

    load_stage(0, 0);
    load_stage(1, BK);

#pragma unroll 1
    for (int ch = 0; ch < KCH; ch++) {
        if (ch + 1 < KCH) asm volatile("cp.async.wait_group 1;\n");
        else              asm volatile("cp.async.wait_group 0;\n");
        __syncthreads();

        uint32_t stA = smem_base + (ch % 3) * STAGE_BYTES;
        uint32_t stB = stA + BM * 128;

        load_frags(0, stA, stB, 0);
        load_frags(1, stA, stB, 1);   // prefetch ks1
        mma_frags(0);                 // ks0
        if (ch + 2 < KCH) load_stage((ch + 2) % 3, (ch + 2) * BK);
        load_frags(0, stA, stB, 2);   // prefetch ks2
        mma_frags(1);                 // ks1
        load_frags(1, stA, stB, 3);   // prefetch ks3
        mma_frags(0);                 // ks2
        mma_frags(1);                 // ks3
    }
    __syncthreads();

    // stage accumulators through smem (stride 132 floats)
#pragma unroll
    for (int mt = 0; mt < 4; mt++) {
        int r0 = wm * 64 + mt * 16 + (l >> 2);
#pragma unroll
        for (int nf = 0; nf < 8; nf++) {
            int col = wn * 64 + nf * 8 + (l & 3) * 2;
            stg[r0 * 132 + col]           = cf[mt][nf][0];
            stg[r0 * 132 + col + 1]       = cf[mt][nf][1];
            stg[(r0 + 8) * 132 + col]     = cf[mt][nf][2];
            stg[(r0 + 8) * 132 + col + 1] = cf[mt][nf][3];
        }
    }
    __syncthreads();

    float a0c = g_coef[t][0], a1c = g_coef[t][1], a2c = g_coef[t][2];
    float a3c = g_coef[t][3], a4c = g_coef[t][4], a5c = g_coef[t][5];

#pragma unroll 1
    for (int pass = 0; pass < 32; pass++) {
        int r = pass * 4 + (tid >> 5);
        int col = (tid & 31) * 4;
        int gi = m0 + r;
        int dj = gi - (n0 + col);          // 0..3 => diagonal hit
        size_t o = baseT + (size_t)gi * NN + (n0 + col);
        float v0 = stg[r * 132 + col],     v1 = stg[r * 132 + col + 1];
        float v2 = stg[r * 132 + col + 2], v3 = stg[r * 132 + col + 3];

        if (phase == 0) {
            uint2 gv = *reinterpret_cast<const uint2*>(g_Gh + o);
            __half2 g01 = *reinterpret_cast<__half2*>(&gv.x);
            __half2 g23 = *reinterpret_cast<__half2*>(&gv.y);
            float q0 = a5c * v0 + a4c * __low2float(g01)  + (dj == 0 ? a3c : 0.f);
            float q1 = a5c * v1 + a4c * __high2float(g01) + (dj == 1 ? a3c : 0.f);
            float q2 = a5c * v2 + a4c * __low2float(g23)  + (dj == 2 ? a3c : 0.f);
            float q3 = a5c * v3 + a4c * __high2float(g23) + (dj == 3 ? a3c : 0.f);
            union { uint2 u; __half2 h[2]; } p, q;
            p.h[0] = __floats2half2_rn(v0, v1); p.h[1] = __floats2half2_rn(v2, v3);
            q.h[0] = __floats2half2_rn(q0, q1); q.h[1] = __floats2half2_rn(q2, q3);
            *reinterpret_cast<uint2*>(g_G2h + o) = p.u;
            *reinterpret_cast<uint2*>(g_Qh + o)  = q.u;
        } else if (phase == 1) {
            union { uint2 u; __half2 h[2]; } p;
            p.h[0] = __floats2half2_rn(v0, v1); p.h[1] = __floats2half2_rn(v2, v3);
            *reinterpret_cast<uint2*>(g_G3h + o) = p.u;
        } else {
            uint2 gv = *reinterpret_cast<const uint2*>(g_Gh + o);
            uint2 g2 = *reinterpret_cast<const uint2*>(g_G2h + o);
            __half2 g01 = *reinterpret_cast<__half2*>(&gv.x);
            __half2 g23 = *reinterpret_cast<__half2*>(&gv.y);
            __half2 h01 = *reinterpret_cast<__half2*>(&g2.x);
            __half2 h23 = *reinterpret_cast<__half2*>(&g2.y);
            float4 rr;
            rr.x = v0 + a2c * __low2float(h01)  + a1c * __low2float(g01)  + (dj == 0 ? a0c : 0.f);
            rr.y = v1 + a2c * __high2float(h01) + a1c * __high2float(g01) + (dj == 1 ? a0c : 0.f);
            rr.z = v2 + a2c * __low2float(h23)  + a1c * __low2float(g23)  + (dj == 2 ? a0c : 0.f);
            rr.w = v3 + a2c * __high2float(h23) + a1c * __high2float(g23) + (dj == 3 ? a0c : 0.f);
            *reinterpret_cast<float4*>(g_acc + o) = rr;
        }
    }

    // signal completion (phases 0 and 1 feed a consumer)
    if (phase < 2) {
        __syncthreads();
        if (tid == 0) {
            __threadfence();
            if (phase == 0) atomicAdd(&g_c0[t][mb], 1);
            else            atomicAdd(&g_c1[t], 1);
        }
    }
}

// -------------------------------------------------------------------------
// LayerNorm over acc rows -> out[i][t][j]  (dedicated high-occupancy kernel)
// -------------------------------------------------------------------------
__global__ __launch_bounds__(256) void ln_kernel(const float* __restrict__ gamma,
                                                 const float* __restrict__ beta,
                                                 float* __restrict__ out) {
    int row = blockIdx.x;
    int t = row / NN, i = row - t * NN;
    const float4* a = reinterpret_cast<const float4*>(g_acc + ((size_t)t * NN + i) * NN);

    float4 v[2];
    float s = 0.f, ss = 0.f;
#pragma unroll
    for (int q = 0; q < 2; q++) {
        v[q] = a[threadIdx.x + q * 256];
        s  += v[q].x + v[q].y + v[q].z + v[q].w;
        ss += v[q].x * v[q].x + v[q].y * v[q].y + v[q].z * v[q].z + v[q].w * v[q].w;
    }
    __shared__ float rs[8], rss[8];
    for (int o = 16; o; o >>= 1) {
        s  += __shfl_down_sync(0xffffffffu, s, o);
        ss += __shfl_down_sync(0xffffffffu, ss, o);
    }
    if ((threadIdx.x & 31) == 0) { rs[threadIdx.x >> 5] = s; rss[threadIdx.x >> 5] = ss; }
    __syncthreads();
    if (threadIdx.x == 0) {
        float t1 = 0.f, t2 = 0.f;
#pragma unroll
        for (int q = 0; q < 8; q++) { t1 += rs[q]; t2 += rss[q]; }
        rs[0] = t1; rss[0] = t2;
    }
    __syncthreads();
    float mu = rs[0] * (1.f / NN);
    float var = rss[0] * (1.f / NN) - mu * mu;
    float rstd = rsqrtf(var + LN_EPS);

    float4* o = reinterpret_cast<float4*>(out + ((size_t)i * NT + t) * NN);
    const float4* gm = reinterpret_cast<const float4*>(gamma);
    const float4* bt = reinterpret_cast<const float4*>(beta);
#pragma unroll
    for (int q = 0; q < 2; q++) {
        int idx = threadIdx.x + q * 256;
        float4 g = gm[idx], b = bt[idx];
        float4 r;
        r.x = (v[q].x - mu) * rstd * g.x + b.x;
        r.y = (v[q].y - mu) * rstd * g.y + b.y;
        r.z = (v[q].z - mu) * rstd * g.z + b.z;
        r.w = (v[q].w - mu) * rstd * g.w + b.w;
        o[idx] = r;
    }
}

extern "C" void kernel_launch(void* const* d_in, const int* in_sizes, int n_in,
                              void* d_out, int out_size) {
    const float* x      = (const float*)d_in[0];
    const float* weight = (const float*)d_in[1];
    const float* gamma  = (const float*)d_in[2];
    const float* beta   = (const float*)d_in[3];
    float* out = (float*)d_out;

    cudaFuncSetAttribute(gemm_fused_kernel,
                         cudaFuncAttributeMaxDynamicSharedMemorySize, SMEM_DYN);

    prep_kernel<<<NT * NN, 256>>>(x, weight);
    gemm_fused_kernel<<<3 * CTAS_PER_PHASE, 128, SMEM_DYN>>>();
    ln_kernel<<<NT * NN, 256>>>(gamma, beta, out);
}

// round 15
// speedup vs baseline: 1.0614x; 1.0295x over previous
#include <cuda_runtime.h>
#include <cuda_fp16.h>
#include <cstdint>

#define NN 2048
#define NT 10
#define KK 5
constexpr float LN_EPS = 1e-5f;

// GEMM tiling: CTA 128x128, BK=64, 4 warps (2x2), warp tile 64x64, 3 stages
// 2 CTAs/SM. 3 GEMM phases fused in one launch with coarse per-(phase,t)
// flag dependencies (R11 structure). prep/LN dedicated high-occupancy kernels.
#define BM 128
#define BN 128
#define BK 64
#define KCH (NN / BK)                          // 32
#define STAGE_BYTES (BM * 128 + BK * 256)      // A 16KB + B 16KB = 32KB
#define SMEM_DYN (3 * STAGE_BYTES + 1024)      // 99328
#define TILES_PER_T 256                        // 16x16
#define TILES_PER_PHASE (NT * TILES_PER_T)     // 2560

// Scratch (__device__ globals; allocation-free rule)
__device__ __half g_Gh [(size_t)NT * NN * NN];  // G_norm
__device__ __half g_G2h[(size_t)NT * NN * NN];  // G^2
__device__ __half g_G3h[(size_t)NT * NN * NN];  // G^3
__device__ __half g_Qh [(size_t)NT * NN * NN];  // Q = a5 G^2 + a4 G + a3 I
__device__ float  g_acc[(size_t)NT * NN * NN];  // pre-LN accumulator (fp32)
__device__ float  g_coef[NT][6];
__device__ int    g_done[2][NT];                // tile-completion counters

__device__ __forceinline__ float clip01(float v) { return fminf(fmaxf(v, 0.f), 1.f); }

__device__ __forceinline__ void cpasync16(uint32_t s, const void* g) {
    asm volatile("cp.async.cg.shared.global [%0], [%1], 16;\n" :: "r"(s), "l"(g));
}
__device__ __forceinline__ void ldsm4(uint32_t* r, uint32_t addr) {
    asm volatile("ldmatrix.sync.aligned.m8n8.x4.shared.b16 {%0,%1,%2,%3}, [%4];"
                 : "=r"(r[0]), "=r"(r[1]), "=r"(r[2]), "=r"(r[3]) : "r"(addr));
}
__device__ __forceinline__ void ldsm4t(uint32_t* r, uint32_t addr) {
    asm volatile("ldmatrix.sync.aligned.m8n8.x4.trans.shared.b16 {%0,%1,%2,%3}, [%4];"
                 : "=r"(r[0]), "=r"(r[1]), "=r"(r[2]), "=r"(r[3]) : "r"(addr));
}
__device__ __forceinline__ void mma16816(float* c, const uint32_t* a,
                                         uint32_t b0, uint32_t b1) {
    asm volatile("mma.sync.aligned.m16n8k16.row.col.f32.f16.f16.f32 "
                 "{%0,%1,%2,%3}, {%4,%5,%6,%7}, {%8,%9}, {%0,%1,%2,%3};"
                 : "+f"(c[0]), "+f"(c[1]), "+f"(c[2]), "+f"(c[3])
                 : "r"(a[0]), "r"(a[1]), "r"(a[2]), "r"(a[3]), "r"(b0), "r"(b1));
}

// -------------------------------------------------------------------------
// prep: per (t,i) row — degree + row-normalize -> g_Gh (fp16).
// Block 0 also computes the polynomial coefficients and zeroes the
// dependency counters (visible to the fused launch via the stream boundary).
// -------------------------------------------------------------------------
__global__ __launch_bounds__(256) void prep_kernel(const float* __restrict__ x,
                                                   const float* __restrict__ w) {
    if (blockIdx.x == 0) {
        int id = threadIdx.x;
        if (id < 2 * NT) ((int*)g_done)[id] = 0;
        if (id < NT) {
            int t = id;
            float c[6] = {1.f, 0.f, 0.f, 0.f, 0.f, 0.f};
            float a[6] = {0.f, 0.f, 0.f, 0.f, 0.f, 0.f};
            for (int k = 0; k < KK; k++) {
                float wk = clip01(w[t * KK + k]);
                float nc[6];
                nc[0] = 1.f - wk;
#pragma unroll
                for (int m = 1; m < 6; m++) nc[m] = wk * c[m - 1];
#pragma unroll
                for (int m = 0; m < 6; m++) { c[m] = nc[m]; a[m] += nc[m]; }
            }
#pragma unroll
            for (int m = 0; m < 6; m++) g_coef[t][m] = a[m];
        }
    }

    int row = blockIdx.x;
    int t = row / NN, i = row - t * NN;
    const float4* xr = reinterpret_cast<const float4*>(x + ((size_t)i * NT + t) * NN);

    float4 v[2];
    float s = 0.f;
#pragma unroll
    for (int q = 0; q < 2; q++) {
        v[q] = xr[threadIdx.x + q * 256];
        s += v[q].x + v[q].y + v[q].z + v[q].w;
    }
    __shared__ float red[8];
    for (int o = 16; o; o >>= 1) s += __shfl_down_sync(0xffffffffu, s, o);
    if ((threadIdx.x & 31) == 0) red[threadIdx.x >> 5] = s;
    __syncthreads();
    if (threadIdx.x == 0) {
        float tt = 0.f;
#pragma unroll
        for (int q = 0; q < 8; q++) tt += red[q];
        red[0] = tt;
    }
    __syncthreads();
    float inv = 1.f / (red[0] + 1e-8f);
    size_t base = ((size_t)t * NN + i) * NN;
#pragma unroll
    for (int q = 0; q < 2; q++) {
        int j0 = (threadIdx.x + q * 256) * 4;
        *reinterpret_cast<__half2*>(&g_Gh[base + j0]) =
            __floats2half2_rn(v[q].x * inv, v[q].y * inv);
        *reinterpret_cast<__half2*>(&g_Gh[base + j0 + 2]) =
            __floats2half2_rn(v[q].z * inv, v[q].w * inv);
    }
}

// -------------------------------------------------------------------------
// Fused 3-phase GEMM, one launch (grid 3*2560):
//   phase 0: G2 = G*G    (writes G2h, Qh)       -> g_done[0][t]
//   phase 1: G3 = G2*G   (writes G3h)           -> g_done[1][t]
//   phase 2: R  = Q*G3   (writes g_acc = R + a2 G2 + a1 G + a0 I)
// Consumers spin on the producer phase's per-t tile counter.
// -------------------------------------------------------------------------
__global__ __launch_bounds__(128, 2) void gemm_fused_kernel() {
    extern __shared__ unsigned char dsm_raw[];
    uint32_t dsm = (uint32_t)__cvta_generic_to_shared(dsm_raw);
    uint32_t smem_base = (dsm + 1023) & ~1023u;
    float* stg = reinterpret_cast<float*>(dsm_raw + (smem_base - dsm));

    int tid = threadIdx.x;
    int l = tid & 31, wid = tid >> 5;
    int wm = wid & 1, wn = wid >> 1;     // 2x2 warp grid

    int bid = blockIdx.x;
    int phase = bid / TILES_PER_PHASE;
    int rem = bid - phase * TILES_PER_PHASE;
    int t = rem / TILES_PER_T;
    int tile = rem - t * TILES_PER_T;
    int m0 = (tile >> 4) * BM;
    int n0 = (tile & 15) * BN;
    size_t baseT = (size_t)t * NN * NN;

    // wait for producer phase (per-t granularity)
    if (phase > 0) {
        if (tid == 0) {
            volatile int* flag = &g_done[phase - 1][t];
            while (atomicAdd((int*)flag, 0) < TILES_PER_T) __nanosleep(128);
            __threadfence();
        }
        __syncthreads();
    }

    const __half *A, *B;
    if (phase == 0)      { A = g_Gh;  B = g_Gh;  }
    else if (phase == 1) { A = g_G2h; B = g_Gh;  }
    else                 { A = g_Qh;  B = g_G3h; }

    float cf[4][8][4];
#pragma unroll
    for (int mt = 0; mt < 4; mt++)
#pragma unroll
        for (int nf = 0; nf < 8; nf++)
#pragma unroll
            for (int e = 0; e < 4; e++) cf[mt][nf][e] = 0.f;

    uint32_t xorv  = (uint32_t)((l & 7) << 4);
    uint32_t a_row = (uint32_t)(wm * 64 + (l & 15));
    uint32_t a_kb  = (uint32_t)((l >> 4) << 4);
    uint32_t b_k0  = (uint32_t)(l & 15);
    uint32_t b_nb  = (uint32_t)(wn * 128 + ((l >> 4) << 4));   // bytes

    auto load_stage = [&](int s, int kk) {
        uint32_t stA = smem_base + s * STAGE_BYTES;
        uint32_t stB = stA + BM * 128;
        const __half* Ab = A + baseT + (size_t)m0 * NN + kk;
        const __half* Bb = B + baseT + (size_t)kk * NN + n0;
#pragma unroll
        for (int q = 0; q < 8; q++) {            // A: 1024 16B chunks
            int id = tid + q * 128;
            int row = id >> 3, kc = id & 7;
            cpasync16(stA + ((uint32_t)(row << 7) + (((uint32_t)(kc << 4)) ^ ((uint32_t)(row & 7) << 4))),
                      Ab + (size_t)row * NN + kc * 8);
        }
#pragma unroll
        for (int q = 0; q < 8; q++) {            // B: 1024 16B chunks
            int id = tid + q * 128;
            int k = id >> 4, nc = id & 15;
            cpasync16(stB + ((uint32_t)(k << 8) + (((uint32_t)(nc << 4)) ^ ((uint32_t)(k & 7) << 4))),
                      Bb + (size_t)k * NN + nc * 8);
        }
        asm volatile("cp.async.commit_group;\n");
    };

    uint32_t af[2][4][4], bf[2][4][4];

    auto load_frags = [&](int buf, uint32_t stA, uint32_t stB, int ks) {
#pragma unroll
        for (int mt = 0; mt < 4; mt++)
            ldsm4(af[buf][mt], stA + ((a_row + mt * 16) << 7) + ((a_kb + ks * 32) ^ xorv));
#pragma unroll
        for (int np = 0; np < 4; np++)
            ldsm4t(bf[buf][np], stB + ((b_k0 + ks * 16) << 8) + ((b_nb + np * 32) ^ xorv));
    };
    auto mma_frags = [&](int buf) {
#pragma unroll
        for (int mt = 0; mt < 4; mt++)
#pragma unroll
            for (int np = 0; np < 4; np++) {
                mma16816(cf[mt][np * 2],     af[buf][mt], bf[buf][np][0], bf[buf][np][1]);
                mma16816(cf[mt][np * 2 + 1], af[buf][mt], bf[buf][np][2], bf[buf][np][3]);
            }
    };

    load_stage(0, 0);
    load_stage(1, BK);

#pragma unroll 1
    for (int ch = 0; ch < KCH; ch++) {
        if (ch + 1 < KCH) asm volatile("cp.async.wait_group 1;\n");
        else              asm volatile("cp.async.wait_group 0;\n");
        __syncthreads();

        uint32_t stA = smem_base + (ch % 3) * STAGE_BYTES;
        uint32_t stB = stA + BM * 128;

        load_frags(0, stA, stB, 0);
        load_frags(1, stA, stB, 1);   // prefetch ks1
        mma_frags(0);                 // ks0
        if (ch + 2 < KCH) load_stage((ch + 2) % 3, (ch + 2) * BK);
        load_frags(0, stA, stB, 2);   // prefetch ks2
        mma_frags(1);                 // ks1
        load_frags(1, stA, stB, 3);   // prefetch ks3
        mma_frags(0);                 // ks2
        mma_frags(1);                 // ks3
    }
    __syncthreads();

    // stage accumulators through smem (stride 132 floats)
#pragma unroll
    for (int mt = 0; mt < 4; mt++) {
        int r0 = wm * 64 + mt * 16 + (l >> 2);
#pragma unroll
        for (int nf = 0; nf < 8; nf++) {
            int col = wn * 64 + nf * 8 + (l & 3) * 2;
            stg[r0 * 132 + col]           = cf[mt][nf][0];
            stg[r0 * 132 + col + 1]       = cf[mt][nf][1];
            stg[(r0 + 8) * 132 + col]     = cf[mt][nf][2];
            stg[(r0 + 8) * 132 + col + 1] = cf[mt][nf][3];
        }
    }
    __syncthreads();

    float a0c = g_coef[t][0], a1c = g_coef[t][1], a2c = g_coef[t][2];
    float a3c = g_coef[t][3], a4c = g_coef[t][4], a5c = g_coef[t][5];

#pragma unroll 1
    for (int pass = 0; pass < 32; pass++) {
        int r = pass * 4 + (tid >> 5);
        int col = (tid & 31) * 4;
        int gi = m0 + r;
        int dj = gi - (n0 + col);          // 0..3 => diagonal hit
        size_t o = baseT + (size_t)gi * NN + (n0 + col);
        float v0 = stg[r * 132 + col],     v1 = stg[r * 132 + col + 1];
        float v2 = stg[r * 132 + col + 2], v3 = stg[r * 132 + col + 3];

        if (phase == 0) {
            uint2 gv = *reinterpret_cast<const uint2*>(g_Gh + o);
            __half2 g01 = *reinterpret_cast<__half2*>(&gv.x);
            __half2 g23 = *reinterpret_cast<__half2*>(&gv.y);
            float q0 = a5c * v0 + a4c * __low2float(g01)  + (dj == 0 ? a3c : 0.f);
            float q1 = a5c * v1 + a4c * __high2float(g01) + (dj == 1 ? a3c : 0.f);
            float q2 = a5c * v2 + a4c * __low2float(g23)  + (dj == 2 ? a3c : 0.f);
            float q3 = a5c * v3 + a4c * __high2float(g23) + (dj == 3 ? a3c : 0.f);
            union { uint2 u; __half2 h[2]; } p, q;
            p.h[0] = __floats2half2_rn(v0, v1); p.h[1] = __floats2half2_rn(v2, v3);
            q.h[0] = __floats2half2_rn(q0, q1); q.h[1] = __floats2half2_rn(q2, q3);
            *reinterpret_cast<uint2*>(g_G2h + o) = p.u;
            *reinterpret_cast<uint2*>(g_Qh + o)  = q.u;
        } else if (phase == 1) {
            union { uint2 u; __half2 h[2]; } p;
            p.h[0] = __floats2half2_rn(v0, v1); p.h[1] = __floats2half2_rn(v2, v3);
            *reinterpret_cast<uint2*>(g_G3h + o) = p.u;
        } else {
            uint2 gv = *reinterpret_cast<const uint2*>(g_Gh + o);
            uint2 g2 = *reinterpret_cast<const uint2*>(g_G2h + o);
            __half2 g01 = *reinterpret_cast<__half2*>(&gv.x);
            __half2 g23 = *reinterpret_cast<__half2*>(&gv.y);
            __half2 h01 = *reinterpret_cast<__half2*>(&g2.x);
            __half2 h23 = *reinterpret_cast<__half2*>(&g2.y);
            float4 rr;
            rr.x = v0 + a2c * __low2float(h01)  + a1c * __low2float(g01)  + (dj == 0 ? a0c : 0.f);
            rr.y = v1 + a2c * __high2float(h01) + a1c * __high2float(g01) + (dj == 1 ? a0c : 0.f);
            rr.z = v2 + a2c * __low2float(h23)  + a1c * __low2float(g23)  + (dj == 2 ? a0c : 0.f);
            rr.w = v3 + a2c * __high2float(h23) + a1c * __high2float(g23) + (dj == 3 ? a0c : 0.f);
            *reinterpret_cast<float4*>(g_acc + o) = rr;
        }
    }

    // signal completion (phases 0 and 1 feed a consumer)
    if (phase < 2) {
        __syncthreads();
        if (tid == 0) {
            __threadfence();
            atomicAdd(&g_done[phase][t], 1);
        }
    }
}

// -------------------------------------------------------------------------
// LayerNorm over acc rows -> out[i][t][j]  (dedicated high-occupancy kernel)
// -------------------------------------------------------------------------
__global__ __launch_bounds__(256) void ln_kernel(const float* __restrict__ gamma,
                                                 const float* __restrict__ beta,
                                                 float* __restrict__ out) {
    int row = blockIdx.x;
    int t = row / NN, i = row - t * NN;
    const float4* a = reinterpret_cast<const float4*>(g_acc + ((size_t)t * NN + i) * NN);

    float4 v[2];
    float s = 0.f, ss = 0.f;
#pragma unroll
    for (int q = 0; q < 2; q++) {
        v[q] = a[threadIdx.x + q * 256];
        s  += v[q].x + v[q].y + v[q].z + v[q].w;
        ss += v[q].x * v[q].x + v[q].y * v[q].y + v[q].z * v[q].z + v[q].w * v[q].w;
    }
    __shared__ float rs[8], rss[8];
    for (int o = 16; o; o >>= 1) {
        s  += __shfl_down_sync(0xffffffffu, s, o);
        ss += __shfl_down_sync(0xffffffffu, ss, o);
    }
    if ((threadIdx.x & 31) == 0) { rs[threadIdx.x >> 5] = s; rss[threadIdx.x >> 5] = ss; }
    __syncthreads();
    if (threadIdx.x == 0) {
        float t1 = 0.f, t2 = 0.f;
#pragma unroll
        for (int q = 0; q < 8; q++) { t1 += rs[q]; t2 += rss[q]; }
        rs[0] = t1; rss[0] = t2;
    }
    __syncthreads();
    float mu = rs[0] * (1.f / NN);
    float var = rss[0] * (1.f / NN) - mu * mu;
    float rstd = rsqrtf(var + LN_EPS);

    float4* o = reinterpret_cast<float4*>(out + ((size_t)i * NT + t) * NN);
    const float4* gm = reinterpret_cast<const float4*>(gamma);
    const float4* bt = reinterpret_cast<const float4*>(beta);
#pragma unroll
    for (int q = 0; q < 2; q++) {
        int idx = threadIdx.x + q * 256;
        float4 g = gm[idx], b = bt[idx];
        float4 r;
        r.x = (v[q].x - mu) * rstd * g.x + b.x;
        r.y = (v[q].y - mu) * rstd * g.y + b.y;
        r.z = (v[q].z - mu) * rstd * g.z + b.z;
        r.w = (v[q].w - mu) * rstd * g.w + b.w;
        o[idx] = r;
    }
}

extern "C" void kernel_launch(void* const* d_in, const int* in_sizes, int n_in,
                              void* d_out, int out_size) {
    const float* x      = (const float*)d_in[0];
    const float* weight = (const float*)d_in[1];
    const float* gamma  = (const float*)d_in[2];
    const float* beta   = (const float*)d_in[3];
    float* out = (float*)d_out;

    cudaFuncSetAttribute(gemm_fused_kernel,
                         cudaFuncAttributeMaxDynamicSharedMemorySize, SMEM_DYN);

    prep_kernel<<<NT * NN, 256>>>(x, weight);
    gemm_fused_kernel<<<3 * TILES_PER_PHASE, 128, SMEM_DYN>>>();
    ln_kernel<<<NT * NN, 256>>>(gamma, beta, out);
}